// round 1
// baseline (speedup 1.0000x reference)
#include <cuda_runtime.h>
#include <math.h>

#define Bv   4
#define Cv   64
#define Hv   160
#define Wv   160
#define HWv  (Hv*Wv)
#define KKv  9
#define OMC  27          // 3*KK offset/mask channels
#define CKK  576         // C*KK

#define TILE 32          // pixels per dcn block
#define THREADS_DCN 256
#define CHUNK 72         // ck chunk for weight staging
#define SWPAD 68         // padded row for sW

// scratch (allocation-free: __device__ globals)
__device__ float g_om[Bv*OMC*HWv];    // offset/mask conv output
__device__ float g_mid[Bv*Cv*HWv];    // block-1 output

__device__ __forceinline__ float gelu_exact(float v) {
    return 0.5f * v * (1.0f + erff(v * 0.70710678118654752f));
}

// ---------------------------------------------------------------------------
// offset/mask conv: 27-channel 3x3 conv. 128 threads, each thread 2 pixels,
// 54 register accumulators, weights in shared ([576][27] transposed layout).
// ---------------------------------------------------------------------------
__global__ void offset_conv_kernel(const float* __restrict__ src,
                                   const float* __restrict__ w,     // [27][64][3][3]
                                   const float* __restrict__ bias,  // [27]
                                   float* __restrict__ om)
{
    extern __shared__ float sw[];          // [576][27] + bias[27]
    float* sb = sw + CKK*OMC;
    for (int i = threadIdx.x; i < CKK*OMC; i += blockDim.x) {
        int o = i / CKK, ck = i % CKK;     // global read coalesced
        sw[ck*OMC + o] = w[i];             // stride-27 STS: conflict-free
    }
    if (threadIdx.x < OMC) sb[threadIdx.x] = bias[threadIdx.x];
    __syncthreads();

    int base = blockIdx.x * 256;
    int p0 = base + threadIdx.x;
    int p1 = p0 + 128;
    int b0 = p0 / HWv, r0 = p0 % HWv, y0 = r0 / Wv, x0 = r0 % Wv;
    int b1 = p1 / HWv, r1 = p1 % HWv, y1 = r1 / Wv, x1 = r1 % Wv;

    float acc0[OMC], acc1[OMC];
    #pragma unroll
    for (int o = 0; o < OMC; o++) { acc0[o] = 0.f; acc1[o] = 0.f; }

    const float* s0 = src + (size_t)b0 * Cv * HWv;
    const float* s1 = src + (size_t)b1 * Cv * HWv;

    for (int c = 0; c < Cv; c++) {
        const float* xc0 = s0 + c*HWv;
        const float* xc1 = s1 + c*HWv;
        #pragma unroll
        for (int ky = 0; ky < 3; ky++) {
            int yy0 = y0 + ky - 1, yy1 = y1 + ky - 1;
            bool vy0 = (unsigned)yy0 < (unsigned)Hv;
            bool vy1 = (unsigned)yy1 < (unsigned)Hv;
            #pragma unroll
            for (int kx = 0; kx < 3; kx++) {
                int xx0 = x0 + kx - 1, xx1 = x1 + kx - 1;
                float v0 = (vy0 && (unsigned)xx0 < (unsigned)Wv) ? __ldg(xc0 + yy0*Wv + xx0) : 0.f;
                float v1 = (vy1 && (unsigned)xx1 < (unsigned)Wv) ? __ldg(xc1 + yy1*Wv + xx1) : 0.f;
                const float* wp = &sw[(c*9 + ky*3 + kx)*OMC];
                #pragma unroll
                for (int o = 0; o < OMC; o++) {
                    float wv = wp[o];           // uniform LDS (broadcast)
                    acc0[o] += v0 * wv;
                    acc1[o] += v1 * wv;
                }
            }
        }
    }
    #pragma unroll
    for (int o = 0; o < OMC; o++) {
        om[((size_t)b0*OMC + o)*HWv + y0*Wv + x0] = acc0[o] + sb[o];
        om[((size_t)b1*OMC + o)*HWv + y1*Wv + x1] = acc1[o] + sb[o];
    }
}

// ---------------------------------------------------------------------------
// Fused modulated deformable conv + BN + (residual) + exact GELU.
// Block = one 32-px row tile of one (b, y). 256 threads.
// Phase A: precompute per-(k,px) gather tables with mask folded into weights.
// Phase B (x2 halves of C): sample 288 (c_local,k) rows into shared.
// Phase C: tiled GEMM 64o x 576ck x 32px, each thread 4o x 2px.
// ---------------------------------------------------------------------------
__global__ void dcn_kernel(const float* __restrict__ src,
                           const float* __restrict__ wd,    // [64][576]
                           const float* __restrict__ bng,
                           const float* __restrict__ bnb,
                           const float* __restrict__ bnm,
                           const float* __restrict__ bnv,
                           const float* __restrict__ identity,  // null in pass 1
                           float* __restrict__ out)
{
    extern __shared__ float smem[];
    float* sSamp = smem;                        // [288][32]
    float* sW    = sSamp + 288*TILE;            // [72][68]
    float* sWgt  = sW + CHUNK*SWPAD;            // 4 x [288]
    int*   sIco  = (int*)(sWgt + 4*288);        // 4 x [288]

    const int xt = blockIdx.x;      // 0..4
    const int y  = blockIdx.y;      // 0..159
    const int b  = blockIdx.z;      // 0..3
    const int x0t = xt * TILE;
    const int tid = threadIdx.x;

    // --- Phase A: gather tables, one entry per (k, px) ---
    const float* omB = g_om + (size_t)b*OMC*HWv + y*Wv;
    for (int idx = tid; idx < KKv*TILE; idx += THREADS_DCN) {
        int k = idx / TILE, px = idx % TILE;
        int xx = x0t + px;
        float dy = omB[(2*k  )*HWv + xx];
        float dx = omB[(2*k+1)*HWv + xx];
        float mr = omB[(18+k )*HWv + xx];
        float m  = 1.f / (1.f + expf(-mr));            // sigmoid mask

        float py  = (float)y  - 1.f + (float)(k/3) + dy;
        float pxf = (float)xx - 1.f + (float)(k%3) + dx;
        float yf = floorf(py), xf = floorf(pxf);
        float ly = py - yf,  lx = pxf - xf;
        int iy0 = (int)yf,  ix0 = (int)xf;
        int iy1 = iy0 + 1,  ix1 = ix0 + 1;
        float vy0 = ((unsigned)iy0 < (unsigned)Hv) ? 1.f : 0.f;
        float vy1 = ((unsigned)iy1 < (unsigned)Hv) ? 1.f : 0.f;
        float vx0 = ((unsigned)ix0 < (unsigned)Wv) ? 1.f : 0.f;
        float vx1 = ((unsigned)ix1 < (unsigned)Wv) ? 1.f : 0.f;

        sWgt[0*288+idx] = (1.f-ly)*(1.f-lx)*m*vy0*vx0;
        sWgt[1*288+idx] = (1.f-ly)*lx      *m*vy0*vx1;
        sWgt[2*288+idx] = ly      *(1.f-lx)*m*vy1*vx0;
        sWgt[3*288+idx] = ly      *lx      *m*vy1*vx1;
        sIco[0*288+idx] = min(max(iy0,0),Hv-1);
        sIco[1*288+idx] = min(max(iy1,0),Hv-1);
        sIco[2*288+idx] = min(max(ix0,0),Wv-1);
        sIco[3*288+idx] = min(max(ix1,0),Wv-1);
    }

    float acc[4][2];
    #pragma unroll
    for (int j = 0; j < 4; j++) { acc[j][0] = 0.f; acc[j][1] = 0.f; }

    const int px2 = tid & 15;     // pixel pair id
    const int og  = tid >> 4;     // output-channel group (4 channels)
    const float* srcB = src + (size_t)b*Cv*HWv;

    for (int ph = 0; ph < 2; ph++) {
        __syncthreads();  // tables ready / previous GEMM done with sSamp
        // --- Phase B: sample 288 rows x 32 px ---
        #pragma unroll 4
        for (int i = 0; i < (288*TILE)/THREADS_DCN; i++) {
            int idx = i*THREADS_DCN + tid;
            int row = idx >> 5;           // (c_local*9 + k)
            int px  = idx & 31;
            int cl = row / 9, k = row % 9;
            int g = k*TILE + px;
            const float* xc = srcB + (ph*32 + cl)*HWv;
            int iy0 = sIco[0*288+g], iy1 = sIco[1*288+g];
            int ix0 = sIco[2*288+g], ix1 = sIco[3*288+g];
            float s = sWgt[0*288+g]*__ldg(xc + iy0*Wv + ix0)
                    + sWgt[1*288+g]*__ldg(xc + iy0*Wv + ix1)
                    + sWgt[2*288+g]*__ldg(xc + iy1*Wv + ix0)
                    + sWgt[3*288+g]*__ldg(xc + iy1*Wv + ix1);
            sSamp[row*TILE + px] = s;
        }
        // --- Phase C: GEMM over this half's 288 ck rows ---
        for (int ckc = 0; ckc < 288/CHUNK; ckc++) {
            __syncthreads();
            int ckg0 = ph*288 + ckc*CHUNK;
            #pragma unroll
            for (int e = 0; e < (CHUNK*64)/THREADS_DCN; e++) {
                int idx = e*THREADS_DCN + tid;
                int o = idx / CHUNK, cki = idx % CHUNK;
                sW[cki*SWPAD + o] = wd[o*CKK + ckg0 + cki];
            }
            __syncthreads();
            #pragma unroll 8
            for (int cki = 0; cki < CHUNK; cki++) {
                float4 wv = *(const float4*)&sW[cki*SWPAD + og*4];
                float2 sv = *(const float2*)&sSamp[(ckc*CHUNK + cki)*TILE + px2*2];
                acc[0][0] += wv.x*sv.x; acc[0][1] += wv.x*sv.y;
                acc[1][0] += wv.y*sv.x; acc[1][1] += wv.y*sv.y;
                acc[2][0] += wv.z*sv.x; acc[2][1] += wv.z*sv.y;
                acc[3][0] += wv.w*sv.x; acc[3][1] += wv.w*sv.y;
            }
        }
    }

    // --- epilogue: BN (+ residual) + exact GELU ---
    const int o0 = og*4;
    const int xg = x0t + px2*2;
    float* outp = out + (size_t)b*Cv*HWv + y*Wv + xg;
    const float* idp = identity ? identity + (size_t)b*Cv*HWv + y*Wv + xg : (const float*)0;
    #pragma unroll
    for (int j = 0; j < 4; j++) {
        int o = o0 + j;
        float sc = bng[o] * rsqrtf(bnv[o] + 1e-5f);
        float sh = bnb[o] - bnm[o]*sc;
        #pragma unroll
        for (int p = 0; p < 2; p++) {
            float v = acc[j][p]*sc + sh;
            if (idp) v += idp[(size_t)o*HWv + p];
            outp[(size_t)o*HWv + p] = gelu_exact(v);
        }
    }
}

// ---------------------------------------------------------------------------
extern "C" void kernel_launch(void* const* d_in, const int* in_sizes, int n_in,
                              void* d_out, int out_size)
{
    const float* x      = (const float*)d_in[0];
    const float* w_om1  = (const float*)d_in[1];
    const float* b_om1  = (const float*)d_in[2];
    const float* w_dcn1 = (const float*)d_in[3];
    const float* bn1g   = (const float*)d_in[4];
    const float* bn1b   = (const float*)d_in[5];
    const float* bn1m   = (const float*)d_in[6];
    const float* bn1v   = (const float*)d_in[7];
    const float* w_om2  = (const float*)d_in[8];
    const float* b_om2  = (const float*)d_in[9];
    const float* w_dcn2 = (const float*)d_in[10];
    const float* bn2g   = (const float*)d_in[11];
    const float* bn2b   = (const float*)d_in[12];
    const float* bn2m   = (const float*)d_in[13];
    const float* bn2v   = (const float*)d_in[14];
    float* out = (float*)d_out;

    float* om  = nullptr;
    float* mid = nullptr;
    cudaGetSymbolAddress((void**)&om,  g_om);
    cudaGetSymbolAddress((void**)&mid, g_mid);

    const int smem_off = (CKK*OMC + OMC) * sizeof(float);                 // 62316 B
    const int smem_dcn = (288*TILE + CHUNK*SWPAD + 8*288) * sizeof(float); // 65664 B
    cudaFuncSetAttribute(offset_conv_kernel, cudaFuncAttributeMaxDynamicSharedMemorySize, smem_off);
    cudaFuncSetAttribute(dcn_kernel,         cudaFuncAttributeMaxDynamicSharedMemorySize, smem_dcn);

    dim3 dcn_grid(Wv/TILE, Hv, Bv);   // 5 x 160 x 4

    // block 1
    offset_conv_kernel<<<(Bv*HWv)/256, 128, smem_off>>>(x, w_om1, b_om1, om);
    dcn_kernel<<<dcn_grid, THREADS_DCN, smem_dcn>>>(x, w_dcn1,
        bn1g, bn1b, bn1m, bn1v, nullptr, mid);

    // block 2 (+ residual with original x)
    offset_conv_kernel<<<(Bv*HWv)/256, 128, smem_off>>>(mid, w_om2, b_om2, om);
    dcn_kernel<<<dcn_grid, THREADS_DCN, smem_dcn>>>(mid, w_dcn2,
        bn2g, bn2b, bn2m, bn2v, x, out);
}